// round 14
// baseline (speedup 1.0000x reference)
#include <cuda_runtime.h>
#include <cuda_fp16.h>

#define BB   128
#define TT   256
#define DD   512
#define HH   1024
#define G4   4096
#define CC   1000
#define NCTA 128
#define NTHR 512

// dynamic smem layout (bytes)
// phase C: W slab [32 rows][2064B] = 66048, then 4 zs slabs of 16896
#define C_Z     66048
#define C_ZSLAB 16896
#define DYN_SMEM 133632
// phase B: Wx slab [64 rows][1040B] = 66560

// ---------------- device scratch ----------------
__device__ float g_zx[(size_t)BB * TT * G4];
// x in MMA-fragment-major layout: tile (rt = row>>4, kt = k>>4) is a 512B block
// at (rt*32+kt)*512; lane L = gq*4+tig holds int4 = its 4 A-registers.
__device__ int4  g_xf[BB * TT * DD / 8];
__device__ int4  g_wx4[DD * G4 / 8];                  // Wx fp16 TRANSPOSED [n:4096][k:512]
__device__ int4  g_wpk4[(size_t)NCTA * 32 * HH / 8];  // Wh fp16 [cta][j:32][k:1024]
// h double buffered, fragment-major (64 k-tiles per row-tile)
__device__ int4  g_hb4[2][BB * HH / 8];
__device__ float g_hT[BB * HH];
__device__ unsigned g_gen;
__device__ unsigned g_cnt32[32];   // tree-barrier arrive counters (4 CTAs each)

__device__ __forceinline__ float tanh_ap(float x) {
    float y;
    asm("tanh.approx.f32 %0, %1;" : "=f"(y) : "f"(x));
    return y;
}
__device__ __forceinline__ float sigmoid_ap(float x) {
    return fmaf(0.5f, tanh_ap(0.5f * x), 0.5f);
}

// fp16 mma
__device__ __forceinline__ void mma_f16(float* c, const unsigned* a, unsigned b0, unsigned b1) {
    asm volatile(
        "mma.sync.aligned.m16n8k16.row.col.f32.f16.f16.f32 "
        "{%0,%1,%2,%3}, {%4,%5,%6,%7}, {%8,%9}, {%0,%1,%2,%3};\n"
        : "+f"(c[0]), "+f"(c[1]), "+f"(c[2]), "+f"(c[3])
        : "r"(a[0]), "r"(a[1]), "r"(a[2]), "r"(a[3]), "r"(b0), "r"(b1));
}
__device__ __forceinline__ void ldsm4(unsigned* r, unsigned a) {
    asm volatile("ldmatrix.sync.aligned.m8n8.x4.shared.b16 {%0,%1,%2,%3}, [%4];\n"
                 : "=r"(r[0]), "=r"(r[1]), "=r"(r[2]), "=r"(r[3]) : "r"(a));
}

// ---- tree grid barrier: 32 arrive counters, CTA0/warp0 aggregates & releases ----
__device__ __forceinline__ void grid_arrive(unsigned gen) {
    (void)gen;
    if (threadIdx.x == 0) {
        __threadfence();
        atomicAdd(&g_cnt32[blockIdx.x >> 2], 1u);
    }
}
__device__ __forceinline__ void grid_wait(unsigned &gen) {
    if (blockIdx.x == 0 && threadIdx.x < 32) {
        const unsigned target = 4u * (gen + 1u);
        volatile unsigned* c = &g_cnt32[threadIdx.x];
        for (;;) {
            unsigned v = *c;
            if (__all_sync(0xffffffffu, (int)(v - target) >= 0)) break;
        }
        if (threadIdx.x == 0) {
            __threadfence();
            atomicExch(&g_gen, gen + 1u);
        }
    }
    if (threadIdx.x == 0) {
        volatile unsigned* vg = &g_gen;
        while ((int)(*vg - (gen + 1u)) < 0) {}
        __threadfence();
    }
    __syncthreads();
    gen++;
}
__device__ __forceinline__ void grid_bar(unsigned &gen) {
    __syncthreads();
    grid_arrive(gen);
    grid_wait(gen);
}

__device__ __forceinline__ unsigned packh2(float lo, float hi) {
    __half2 h = __floats2half2_rn(lo, hi);
    return *(unsigned*)&h;
}

extern __shared__ __align__(16) unsigned char smem[];

__global__ void __launch_bounds__(NTHR, 1)
lstm_persistent(const float* __restrict__ x, const float* __restrict__ Wk,
                const float* __restrict__ bk, const float* __restrict__ w,
                const float* __restrict__ bo, float* __restrict__ out) {
    const int tid  = threadIdx.x;
    const int blk  = blockIdx.x;
    const int wid  = tid >> 5;
    const int lane = tid & 31;
    const int gq   = lane >> 2;
    const int tig  = lane & 3;
    const unsigned sb = (unsigned)__cvta_generic_to_shared(smem);

    unsigned gen = atomicAdd(&g_gen, 0u);

    const int gtid = blk * NTHR + tid;
    const int gstr = NCTA * NTHR;

    // ===== Phase A: fp16 conversions + repacks =====
    {
        for (int i = gtid; i < 2048 * 32 * 32; i += gstr) {
            int ln = i & 31, kt = (i >> 5) & 31, rt = i >> 10;
            int gq_ = ln >> 2, tg = ln & 3;
            const float* xr0 = x + (size_t)(rt * 16 + gq_) * DD + kt * 16;
            const float* xr1 = xr0 + 8 * DD;
            float2 v0 = *(const float2*)(xr0 + 2 * tg);
            float2 v1 = *(const float2*)(xr1 + 2 * tg);
            float2 v2 = *(const float2*)(xr0 + 8 + 2 * tg);
            float2 v3 = *(const float2*)(xr1 + 8 + 2 * tg);
            int4 o;
            o.x = (int)packh2(v0.x, v0.y);
            o.y = (int)packh2(v1.x, v1.y);
            o.z = (int)packh2(v2.x, v2.y);
            o.w = (int)packh2(v3.x, v3.y);
            g_xf[i] = o;
        }
        unsigned short* wt = (unsigned short*)g_wx4;
        for (int i = gtid; i < G4 * DD; i += gstr) {
            int n = i >> 9, k = i & 511;
            wt[i] = __half_as_ushort(__float2half_rn(Wk[(size_t)k * G4 + n]));
        }
        unsigned short* wpk = (unsigned short*)g_wpk4;
        for (int i = gtid; i < NCTA * 32 * HH; i += gstr) {
            int k  = i & (HH - 1);
            int j  = (i >> 10) & 31;
            int bq = i >> 15;
            int col = ((j >> 3) << 10) + (bq << 3) + (j & 7);
            wpk[i] = __half_as_ushort(__float2half_rn(Wk[(size_t)(DD + k) * G4 + col]));
        }
        int4 z4 = make_int4(0, 0, 0, 0);
        for (int i = gtid; i < BB * HH / 8; i += gstr) {
            g_hb4[0][i] = z4; g_hb4[1][i] = z4;
        }
    }
    grid_bar(gen);

    // ===== Phase B: Zx = x @ Wx + bk  (2 row-tiles per iter share one W ldsm) =====
    {
        const int n0 = (blk & 63) * 64;
        int4* sB4 = (int4*)smem;
        for (int i = tid; i < 64 * 64; i += NTHR) {
            int r = i >> 6, q = i & 63;
            sB4[r * 65 + q] = g_wx4[(n0 + r) * 64 + q];
        }
        __syncthreads();

        const int wm = wid & 3, wn = wid >> 2;
        const unsigned bko = (unsigned)(((lane >> 3) & 1) << 4);
        const int bn = (lane & 7) + ((lane >> 4) << 3);
        const unsigned wb0 = sb + (unsigned)((wn * 16 + bn) * 1040) + bko;

#pragma unroll 1
        for (int s2 = 0; s2 < 128; s2++) {
            const int rt0 = ((blk >> 6) + 4 * s2) * 4 + wm;
            const int rt1 = rt0 + 8;
            const int4* xf0 = g_xf + (size_t)rt0 * 1024 + lane;
            const int4* xf1 = g_xf + (size_t)rt1 * 1024 + lane;
            float acc[2][2][4] = {};
#pragma unroll 4
            for (int kt = 0; kt < 32; kt++) {
                int4 av0 = __ldg(xf0 + kt * 32);
                int4 av1 = __ldg(xf1 + kt * 32);
                unsigned bh[4];
                ldsm4(bh, wb0 + kt * 32);
                unsigned a0[4] = {(unsigned)av0.x, (unsigned)av0.y, (unsigned)av0.z, (unsigned)av0.w};
                unsigned a1[4] = {(unsigned)av1.x, (unsigned)av1.y, (unsigned)av1.z, (unsigned)av1.w};
                mma_f16(acc[0][0], a0, bh[0], bh[1]);
                mma_f16(acc[0][1], a0, bh[2], bh[3]);
                mma_f16(acc[1][0], a1, bh[0], bh[1]);
                mma_f16(acc[1][1], a1, bh[2], bh[3]);
            }
#pragma unroll
            for (int rr = 0; rr < 2; rr++)
#pragma unroll
                for (int nt = 0; nt < 2; nt++)
#pragma unroll
                    for (int f = 0; f < 4; f++) {
                        int row = (rr ? rt1 : rt0) * 16 + gq + (f >> 1) * 8;
                        int cn  = n0 + wn * 16 + nt * 8 + 2 * tig + (f & 1);
                        g_zx[(size_t)row * G4 + cn] = acc[rr][nt][f] + __ldg(&bk[cn]);
                    }
        }
    }
    grid_bar(gen);

    // ===== Phase C: 256 steps. W smem-resident; h fragments LDG'd from L2;
    //        2-ahead register pipeline; 4 zs slabs; tree barrier with overlap =====
    {
        int4* sW4 = (int4*)smem;
        for (int i = tid; i < 32 * 128; i += NTHR) {
            int j = i >> 7, q = i & 127;
            sW4[j * 129 + q] = g_wpk4[((size_t)blk * 32 + j) * 128 + q];
        }
        __syncthreads();

        const int wm  = wid & 3;    // 4 row groups of 32
        const int ksg = wid >> 2;   // 4 k groups of 256
        const unsigned bko = (unsigned)(((lane >> 3) & 1) << 4);
        const int bn = (lane & 7) + ((lane >> 4) << 3);
        const unsigned wB0 = sb + (unsigned)(bn * 2064) + bko + (unsigned)(ksg * 512);
        const unsigned wB1 = wB0 + 16u * 2064u;
        float* zs0 = (float*)(smem + C_Z);
        float* zs1 = (float*)(smem + C_Z + 1 * C_ZSLAB);
        float* zs2 = (float*)(smem + C_Z + 2 * C_ZSLAB);
        float* zs3 = (float*)(smem + C_Z + 3 * C_ZSLAB);
        float* zsw = (float*)(smem + C_Z + ksg * C_ZSLAB);

        const int gb = tid >> 2;          // batch row owned in epilogue
        const int u0 = (tid & 3) << 1;    // first of 2 hidden units (even)
        float cst[2] = {0.f, 0.f};

        // writer address for h (fragment-major): k = blk*8 + u0 (+1 in same word)
        const int kw  = blk * 8 + u0;
        const int w_tile = ((gb >> 4) * 64 + (kw >> 4));
        const int w_word = ((gb & 7) * 4 + (((kw & 7)) >> 1)) * 4 + (((kw & 15) >> 3) * 2 + ((gb >> 3) & 1));
        const int w_idx = w_tile * 128 + w_word;   // index in half2 units

        float zxr[2][4];
#pragma unroll
        for (int uu = 0; uu < 2; uu++) {
            size_t zb = ((size_t)gb * TT + 0) * G4 + (blk << 3) + u0 + uu;
#pragma unroll
            for (int g = 0; g < 4; g++) zxr[uu][g] = __ldcg(&g_zx[zb + (size_t)g * HH]);
        }

        for (int t = 0; t < TT; t++) {
            const int p = t & 1;
            const int4* hp0 = g_hb4[p] + ((wm * 2 + 0) * 64 + ksg * 16) * 32 + lane;
            const int4* hp1 = g_hb4[p] + ((wm * 2 + 1) * 64 + ksg * 16) * 32 + lane;
            float acc[8][4];
#pragma unroll
            for (int i = 0; i < 8; i++)
#pragma unroll
                for (int f = 0; f < 4; f++) acc[i][f] = 0.f;

            // 2-ahead register-rotated LDG pipeline over 16 k-tiles
            int4 a0[3], a1[3];
            a0[0] = __ldcg(hp0);        a1[0] = __ldcg(hp1);
            a0[1] = __ldcg(hp0 + 32);   a1[1] = __ldcg(hp1 + 32);
#pragma unroll
            for (int ks = 0; ks < 16; ks++) {
                if (ks < 14) {
                    a0[(ks + 2) % 3] = __ldcg(hp0 + (ks + 2) * 32);
                    a1[(ks + 2) % 3] = __ldcg(hp1 + (ks + 2) * 32);
                }
                unsigned b0[4], b1[4];
                ldsm4(b0, wB0 + ks * 32);
                ldsm4(b1, wB1 + ks * 32);
                const int4 v0 = a0[ks % 3];
                const int4 v1 = a1[ks % 3];
                unsigned A0[4] = {(unsigned)v0.x, (unsigned)v0.y, (unsigned)v0.z, (unsigned)v0.w};
                unsigned A1[4] = {(unsigned)v1.x, (unsigned)v1.y, (unsigned)v1.z, (unsigned)v1.w};
                mma_f16(acc[0], A0, b0[0], b0[1]);
                mma_f16(acc[1], A0, b0[2], b0[3]);
                mma_f16(acc[2], A0, b1[0], b1[1]);
                mma_f16(acc[3], A0, b1[2], b1[3]);
                mma_f16(acc[4], A1, b0[0], b0[1]);
                mma_f16(acc[5], A1, b0[2], b0[3]);
                mma_f16(acc[6], A1, b1[0], b1[1]);
                mma_f16(acc[7], A1, b1[2], b1[3]);
            }

            // every warp writes its own slab; ONE sync; gate threads sum 4 slabs
#pragma unroll
            for (int mt = 0; mt < 2; mt++)
#pragma unroll
                for (int ci = 0; ci < 4; ci++)
#pragma unroll
                    for (int f = 0; f < 4; f++) {
                        int row = wm * 32 + mt * 16 + gq + (f >> 1) * 8;
                        int col = ci * 8 + 2 * tig + (f & 1);
                        zsw[row * 33 + col] = acc[mt * 4 + ci][f];
                    }
            __syncthreads();

            // gate math (tanh.approx): thread owns (batch row gb, units u0..u0+1)
            float hnv[2];
#pragma unroll
            for (int uu = 0; uu < 2; uu++) {
                int u = u0 + uu;
                float zi = zs0[gb * 33 + 0 * 8 + u] + zs1[gb * 33 + 0 * 8 + u]
                         + zs2[gb * 33 + 0 * 8 + u] + zs3[gb * 33 + 0 * 8 + u] + zxr[uu][0];
                float zj = zs0[gb * 33 + 1 * 8 + u] + zs1[gb * 33 + 1 * 8 + u]
                         + zs2[gb * 33 + 1 * 8 + u] + zs3[gb * 33 + 1 * 8 + u] + zxr[uu][1];
                float zf = zs0[gb * 33 + 2 * 8 + u] + zs1[gb * 33 + 2 * 8 + u]
                         + zs2[gb * 33 + 2 * 8 + u] + zs3[gb * 33 + 2 * 8 + u] + zxr[uu][2];
                float zo = zs0[gb * 33 + 3 * 8 + u] + zs1[gb * 33 + 3 * 8 + u]
                         + zs2[gb * 33 + 3 * 8 + u] + zs3[gb * 33 + 3 * 8 + u] + zxr[uu][3];
                float cn = cst[uu] * sigmoid_ap(zf + 1.0f) + sigmoid_ap(zi) * tanh_ap(zj);
                hnv[uu] = sigmoid_ap(zo) * tanh_ap(cn);
                cst[uu] = cn;
            }
            {
                __half2 hv = __halves2half2(__float2half_rn(hnv[0]), __float2half_rn(hnv[1]));
                ((__half2*)g_hb4[1 - p])[w_idx] = hv;
            }
            if (t == TT - 1) {
                g_hT[gb * HH + (blk << 3) + u0]     = hnv[0];
                g_hT[gb * HH + (blk << 3) + u0 + 1] = hnv[1];
                grid_bar(gen);
            } else {
                // announce arrival FIRST, then overlap zx prefetch with release propagation
                __syncthreads();
                grid_arrive(gen);
#pragma unroll
                for (int uu = 0; uu < 2; uu++) {
                    size_t zb = ((size_t)gb * TT + (t + 1)) * G4 + (blk << 3) + u0 + uu;
#pragma unroll
                    for (int g = 0; g < 4; g++) zxr[uu][g] = __ldcg(&g_zx[zb + (size_t)g * HH]);
                }
                grid_wait(gen);
            }
        }
    }

    // ===== Phase D: out = hT @ w + bo =====
    {
        float* sh = (float*)smem;
        const int b_ = blk;
        for (int k = tid; k < HH; k += NTHR) sh[k] = g_hT[b_ * HH + k];
        __syncthreads();
        for (int c = tid; c < CC; c += NTHR) {
            float acc = bo[c];
#pragma unroll 8
            for (int k = 0; k < HH; k++) acc = fmaf(sh[k], w[k * CC + c], acc);
            out[b_ * CC + c] = acc;
        }
    }
}

extern "C" void kernel_launch(void* const* d_in, const int* in_sizes, int n_in,
                              void* d_out, int out_size) {
    (void)in_sizes; (void)n_in; (void)out_size;
    const float* x  = (const float*)d_in[0];
    const float* Wk = (const float*)d_in[1];
    const float* bk = (const float*)d_in[2];
    const float* w  = (const float*)d_in[3];
    const float* b  = (const float*)d_in[4];
    float* out = (float*)d_out;
    cudaFuncSetAttribute(lstm_persistent, cudaFuncAttributeMaxDynamicSharedMemorySize, DYN_SMEM);
    lstm_persistent<<<NCTA, NTHR, DYN_SMEM>>>(x, Wk, bk, w, b, out);
}

// round 16
// speedup vs baseline: 1.0868x; 1.0868x over previous
#include <cuda_runtime.h>
#include <cuda_fp16.h>

#define BB   128
#define TT   256
#define DD   512
#define HH   1024
#define G4   4096
#define CC   1000
#define NCTA 128
#define NTHR 1024

// dynamic smem layout (bytes)
// phase C: W slab [32 rows][2064B] = 66048, then 4 zs slabs of 16896
#define C_Z     66048
#define C_ZSLAB 16896
#define DYN_SMEM 133632
// phase B: Wx slab [64 rows][1040B] = 66560

// ---------------- device scratch ----------------
__device__ float g_zx[(size_t)BB * TT * G4];
// x in MMA-fragment-major layout: tile (rt = row>>4, kt = k>>4) is a 512B block
// at (rt*32+kt)*512; lane L = gq*4+tig holds int4 = its 4 A-registers.
__device__ int4  g_xf[BB * TT * DD / 8];
__device__ int4  g_wx4[DD * G4 / 8];                  // Wx fp16 TRANSPOSED [n:4096][k:512]
__device__ int4  g_wpk4[(size_t)NCTA * 32 * HH / 8];  // Wh fp16 [cta][j:32][k:1024]
// h double buffered, fragment-major (64 k-tiles per row-tile)
__device__ int4  g_hb4[2][BB * HH / 8];
__device__ float g_hT[BB * HH];
__device__ unsigned g_gen;
__device__ unsigned g_cnt;

__device__ __forceinline__ float tanh_ap(float x) {
    float y;
    asm("tanh.approx.f32 %0, %1;" : "=f"(y) : "f"(x));
    return y;
}
__device__ __forceinline__ float sigmoid_ap(float x) {
    return fmaf(0.5f, tanh_ap(0.5f * x), 0.5f);
}

// fp16 mma
__device__ __forceinline__ void mma_f16(float* c, const unsigned* a, unsigned b0, unsigned b1) {
    asm volatile(
        "mma.sync.aligned.m16n8k16.row.col.f32.f16.f16.f32 "
        "{%0,%1,%2,%3}, {%4,%5,%6,%7}, {%8,%9}, {%0,%1,%2,%3};\n"
        : "+f"(c[0]), "+f"(c[1]), "+f"(c[2]), "+f"(c[3])
        : "r"(a[0]), "r"(a[1]), "r"(a[2]), "r"(a[3]), "r"(b0), "r"(b1));
}
__device__ __forceinline__ void ldsm4(unsigned* r, unsigned a) {
    asm volatile("ldmatrix.sync.aligned.m8n8.x4.shared.b16 {%0,%1,%2,%3}, [%4];\n"
                 : "=r"(r[0]), "=r"(r[1]), "=r"(r[2]), "=r"(r[3]) : "r"(a));
}

// grid barrier split (round-13 proven): single counter, last arriver releases
__device__ __forceinline__ void grid_arrive(unsigned gen) {
    if (threadIdx.x == 0) {
        __threadfence();
        if (atomicAdd(&g_cnt, 1u) == NCTA - 1u) {
            g_cnt = 0u;
            __threadfence();
            atomicExch(&g_gen, gen + 1u);
        }
    }
}
__device__ __forceinline__ void grid_wait(unsigned &gen) {
    if (threadIdx.x == 0) {
        volatile unsigned* vg = &g_gen;
        while (*vg == gen) {}
        __threadfence();
    }
    __syncthreads();
    gen++;
}
__device__ __forceinline__ void grid_bar(unsigned &gen) {
    __syncthreads();
    grid_arrive(gen);
    grid_wait(gen);
}

__device__ __forceinline__ unsigned packh2(float lo, float hi) {
    __half2 h = __floats2half2_rn(lo, hi);
    return *(unsigned*)&h;
}

extern __shared__ __align__(16) unsigned char smem[];

__global__ void __launch_bounds__(NTHR, 1)
lstm_persistent(const float* __restrict__ x, const float* __restrict__ Wk,
                const float* __restrict__ bk, const float* __restrict__ w,
                const float* __restrict__ bo, float* __restrict__ out) {
    const int tid  = threadIdx.x;
    const int blk  = blockIdx.x;
    const int wid  = tid >> 5;
    const int lane = tid & 31;
    const int gq   = lane >> 2;
    const int tig  = lane & 3;
    const unsigned sb = (unsigned)__cvta_generic_to_shared(smem);

    unsigned gen = atomicAdd(&g_gen, 0u);

    const int gtid = blk * NTHR + tid;
    const int gstr = NCTA * NTHR;

    // ===== Phase A: fp16 conversions + repacks =====
    {
        for (int i = gtid; i < 2048 * 32 * 32; i += gstr) {
            int ln = i & 31, kt = (i >> 5) & 31, rt = i >> 10;
            int gq_ = ln >> 2, tg = ln & 3;
            const float* xr0 = x + (size_t)(rt * 16 + gq_) * DD + kt * 16;
            const float* xr1 = xr0 + 8 * DD;
            float2 v0 = *(const float2*)(xr0 + 2 * tg);
            float2 v1 = *(const float2*)(xr1 + 2 * tg);
            float2 v2 = *(const float2*)(xr0 + 8 + 2 * tg);
            float2 v3 = *(const float2*)(xr1 + 8 + 2 * tg);
            int4 o;
            o.x = (int)packh2(v0.x, v0.y);
            o.y = (int)packh2(v1.x, v1.y);
            o.z = (int)packh2(v2.x, v2.y);
            o.w = (int)packh2(v3.x, v3.y);
            g_xf[i] = o;
        }
        unsigned short* wt = (unsigned short*)g_wx4;
        for (int i = gtid; i < G4 * DD; i += gstr) {
            int n = i >> 9, k = i & 511;
            wt[i] = __half_as_ushort(__float2half_rn(Wk[(size_t)k * G4 + n]));
        }
        unsigned short* wpk = (unsigned short*)g_wpk4;
        for (int i = gtid; i < NCTA * 32 * HH; i += gstr) {
            int k  = i & (HH - 1);
            int j  = (i >> 10) & 31;
            int bq = i >> 15;
            int col = ((j >> 3) << 10) + (bq << 3) + (j & 7);
            wpk[i] = __half_as_ushort(__float2half_rn(Wk[(size_t)(DD + k) * G4 + col]));
        }
        int4 z4 = make_int4(0, 0, 0, 0);
        for (int i = gtid; i < BB * HH / 8; i += gstr) {
            g_hb4[0][i] = z4; g_hb4[1][i] = z4;
        }
    }
    grid_bar(gen);

    // ===== Phase B: Zx = x @ Wx + bk  (32 warps: 8 tile-slots x 4 n-quarters) =====
    {
        const int n0 = (blk & 63) * 64;
        const int grp = blk >> 6;
        int4* sB4 = (int4*)smem;
        for (int i = tid; i < 64 * 64; i += NTHR) {
            int r = i >> 6, q = i & 63;
            sB4[r * 65 + q] = g_wx4[(n0 + r) * 64 + q];
        }
        __syncthreads();

        const int wt8 = wid & 7;            // 8 tile slots
        const int wn  = wid >> 3;           // 4 n-quarters (16 cols each)
        const unsigned bko = (unsigned)(((lane >> 3) & 1) << 4);
        const int bn = (lane & 7) + ((lane >> 4) << 3);
        const unsigned wb0 = sb + (unsigned)((wn * 16 + bn) * 1040) + bko;

#pragma unroll 1
        for (int s2 = 0; s2 < 128; s2++) {
            const int rt = (grp + 4 * s2 + 2 * (wt8 >> 2)) * 4 + (wt8 & 3);
            const int4* xf = g_xf + (size_t)rt * 1024 + lane;
            float acc[2][4] = {};
#pragma unroll 8
            for (int kt = 0; kt < 32; kt++) {
                int4 av = __ldg(xf + kt * 32);
                unsigned bh[4];
                ldsm4(bh, wb0 + kt * 32);
                unsigned a[4] = {(unsigned)av.x, (unsigned)av.y, (unsigned)av.z, (unsigned)av.w};
                mma_f16(acc[0], a, bh[0], bh[1]);
                mma_f16(acc[1], a, bh[2], bh[3]);
            }
#pragma unroll
            for (int nt = 0; nt < 2; nt++)
#pragma unroll
                for (int f = 0; f < 4; f++) {
                    int row = rt * 16 + gq + (f >> 1) * 8;
                    int cn  = n0 + wn * 16 + nt * 8 + 2 * tig + (f & 1);
                    g_zx[(size_t)row * G4 + cn] = acc[nt][f] + __ldg(&bk[cn]);
                }
        }
    }
    grid_bar(gen);

    // ===== Phase C: 256 steps. 32 warps: 8 row-groups x 4 k-groups;
    //        W smem-resident; h fragments LDG'd from L2; 1-ahead pipeline =====
    {
        int4* sW4 = (int4*)smem;
        for (int i = tid; i < 32 * 128; i += NTHR) {
            int j = i >> 7, q = i & 127;
            sW4[j * 129 + q] = g_wpk4[((size_t)blk * 32 + j) * 128 + q];
        }
        __syncthreads();

        const int wm  = wid & 7;    // 8 row groups of 16
        const int ksg = wid >> 3;   // 4 k groups of 256
        const unsigned bko = (unsigned)(((lane >> 3) & 1) << 4);
        const int bn = (lane & 7) + ((lane >> 4) << 3);
        const unsigned wB0 = sb + (unsigned)(bn * 2064) + bko + (unsigned)(ksg * 512);
        const unsigned wB1 = wB0 + 16u * 2064u;
        float* zs0 = (float*)(smem + C_Z);
        float* zs1 = (float*)(smem + C_Z + 1 * C_ZSLAB);
        float* zs2 = (float*)(smem + C_Z + 2 * C_ZSLAB);
        float* zs3 = (float*)(smem + C_Z + 3 * C_ZSLAB);
        float* zsw = (float*)(smem + C_Z + ksg * C_ZSLAB);

        const int gb = tid >> 3;          // batch row owned in epilogue (0..127)
        const int uu = tid & 7;           // single hidden unit
        float cst = 0.f;

        // writer address for h (fragment-major), in __half units
        const int kw  = blk * 8 + uu;
        const int w_tile = ((gb >> 4) * 64 + (kw >> 4));
        const int w_lane = (gb & 7) * 4 + ((kw & 7) >> 1);
        const int w_comp = (((kw >> 3) & 1) << 1) + ((gb >> 3) & 1);
        const int w_hidx = w_tile * 256 + w_lane * 8 + w_comp * 2 + (kw & 1);

        float zxr[4];
        {
            size_t zb = ((size_t)gb * TT + 0) * G4 + (blk << 3) + uu;
#pragma unroll
            for (int g = 0; g < 4; g++) zxr[g] = __ldcg(&g_zx[zb + (size_t)g * HH]);
        }

        for (int t = 0; t < TT; t++) {
            const int p = t & 1;
            const int4* hp = g_hb4[p] + (wm * 64 + ksg * 16) * 32 + lane;
            float acc[4][4];
#pragma unroll
            for (int i = 0; i < 4; i++)
#pragma unroll
                for (int f = 0; f < 4; f++) acc[i][f] = 0.f;

            // 1-ahead LDG pipeline over 16 k-tiles
            int4 av = __ldcg(hp);
#pragma unroll 4
            for (int ks = 0; ks < 16; ks++) {
                int4 nv;
                if (ks < 15) nv = __ldcg(hp + (ks + 1) * 32);
                unsigned b0[4], b1[4];
                ldsm4(b0, wB0 + ks * 32);
                ldsm4(b1, wB1 + ks * 32);
                unsigned A[4] = {(unsigned)av.x, (unsigned)av.y, (unsigned)av.z, (unsigned)av.w};
                mma_f16(acc[0], A, b0[0], b0[1]);
                mma_f16(acc[1], A, b0[2], b0[3]);
                mma_f16(acc[2], A, b1[0], b1[1]);
                mma_f16(acc[3], A, b1[2], b1[3]);
                av = nv;
            }

            // every warp writes its own slab; ONE sync; gate threads sum 4 slabs
#pragma unroll
            for (int ci = 0; ci < 4; ci++)
#pragma unroll
                for (int f = 0; f < 4; f++) {
                    int row = wm * 16 + gq + (f >> 1) * 8;
                    int col = ci * 8 + 2 * tig + (f & 1);
                    zsw[row * 33 + col] = acc[ci][f];
                }
            __syncthreads();

            // gate math (tanh.approx): thread owns (batch row gb, unit uu)
            float zi = zs0[gb * 33 + 0 * 8 + uu] + zs1[gb * 33 + 0 * 8 + uu]
                     + zs2[gb * 33 + 0 * 8 + uu] + zs3[gb * 33 + 0 * 8 + uu] + zxr[0];
            float zj = zs0[gb * 33 + 1 * 8 + uu] + zs1[gb * 33 + 1 * 8 + uu]
                     + zs2[gb * 33 + 1 * 8 + uu] + zs3[gb * 33 + 1 * 8 + uu] + zxr[1];
            float zf = zs0[gb * 33 + 2 * 8 + uu] + zs1[gb * 33 + 2 * 8 + uu]
                     + zs2[gb * 33 + 2 * 8 + uu] + zs3[gb * 33 + 2 * 8 + uu] + zxr[2];
            float zo = zs0[gb * 33 + 3 * 8 + uu] + zs1[gb * 33 + 3 * 8 + uu]
                     + zs2[gb * 33 + 3 * 8 + uu] + zs3[gb * 33 + 3 * 8 + uu] + zxr[3];
            float cn = cst * sigmoid_ap(zf + 1.0f) + sigmoid_ap(zi) * tanh_ap(zj);
            float hn = sigmoid_ap(zo) * tanh_ap(cn);
            cst = cn;

            ((__half*)g_hb4[1 - p])[w_hidx] = __float2half_rn(hn);

            if (t == TT - 1) {
                g_hT[gb * HH + (blk << 3) + uu] = hn;
                grid_bar(gen);
            } else {
                // announce arrival FIRST, then overlap zx prefetch with release propagation
                __syncthreads();
                grid_arrive(gen);
                {
                    size_t zb = ((size_t)gb * TT + (t + 1)) * G4 + (blk << 3) + uu;
#pragma unroll
                    for (int g = 0; g < 4; g++) zxr[g] = __ldcg(&g_zx[zb + (size_t)g * HH]);
                }
                grid_wait(gen);
            }
        }
    }

    // ===== Phase D: out = hT @ w + bo =====
    {
        float* sh = (float*)smem;
        const int b_ = blk;
        for (int k = tid; k < HH; k += NTHR) sh[k] = g_hT[b_ * HH + k];
        __syncthreads();
        for (int c = tid; c < CC; c += NTHR) {
            float acc = bo[c];
#pragma unroll 8
            for (int k = 0; k < HH; k++) acc = fmaf(sh[k], w[k * CC + c], acc);
            out[b_ * CC + c] = acc;
        }
    }
}

extern "C" void kernel_launch(void* const* d_in, const int* in_sizes, int n_in,
                              void* d_out, int out_size) {
    (void)in_sizes; (void)n_in; (void)out_size;
    const float* x  = (const float*)d_in[0];
    const float* Wk = (const float*)d_in[1];
    const float* bk = (const float*)d_in[2];
    const float* w  = (const float*)d_in[3];
    const float* b  = (const float*)d_in[4];
    float* out = (float*)d_out;
    cudaFuncSetAttribute(lstm_persistent, cudaFuncAttributeMaxDynamicSharedMemorySize, DYN_SMEM);
    lstm_persistent<<<NCTA, NTHR, DYN_SMEM>>>(x, Wk, bk, w, b, out);
}